// round 14
// baseline (speedup 1.0000x reference)
#include <cuda_runtime.h>
#include <math.h>

#define T_STEPS 1024
#define BATCH   64
#define DIM     256
#define NB      16              // batch groups = clusters (independent rows)
#define BPG     4               // batches per group
#define NN      8               // column-group CTAs per cluster
#define NPG     32              // columns per CTA
#define NCTA    (NB * NN)       // 128 CTAs
#define TX_BYTES 4096u          // per barrier use: 8 CTAs * 64 owners * 8B

// ---- scratch (static __device__ arrays: allocation-free) ----
__device__ float g_Xz[T_STEPS * BATCH * DIM];   // [((t*8+ng)*16+bg)*128 + bl*32 + nl]
__device__ float g_Xr[T_STEPS * BATCH * DIM];
__device__ float g_Xh[T_STEPS * BATCH * DIM];

// ---- packed fp32x2 helpers (PTX-only f32x2 ops: 2x fp32 throughput) ----
__device__ __forceinline__ unsigned long long pack2(float lo, float hi) {
    unsigned long long r;
    asm("mov.b64 %0, {%1, %2};" : "=l"(r) : "f"(lo), "f"(hi));
    return r;
}
__device__ __forceinline__ float2 unpack2(unsigned long long v) {
    float lo, hi;
    asm("mov.b64 {%0, %1}, %2;" : "=f"(lo), "=f"(hi) : "l"(v));
    return make_float2(lo, hi);
}
__device__ __forceinline__ void ffma2(unsigned long long& d,
                                      unsigned long long a, unsigned long long b) {
    asm("fma.rn.f32x2 %0, %1, %2, %0;" : "+l"(d) : "l"(a), "l"(b));
}
__device__ __forceinline__ unsigned long long addf2(unsigned long long a,
                                                    unsigned long long b) {
    unsigned long long r;
    asm("add.rn.f32x2 %0, %1, %2;" : "=l"(r) : "l"(a), "l"(b));
    return r;
}
__device__ __forceinline__ float sigmoidf_(float x) {
    return 1.0f / (1.0f + __expf(-x));
}
__device__ __forceinline__ float tanh_clamped(float x) {
    x = fminf(fmaxf(x, -20.0f), 20.0f);
    float e = __expf(-2.0f * x);
    return (1.0f - e) / (1.0f + e);
}
__device__ __forceinline__ unsigned long long shflx64(unsigned long long v, int m) {
    return __shfl_xor_sync(0xffffffffu, v, m);
}

// ---- cluster / DSMEM primitives ----
__device__ __forceinline__ unsigned smem_u32(const void* p) {
    unsigned a;
    asm("{ .reg .u64 t; cvta.to.shared.u64 t, %1; cvt.u32.u64 %0, t; }"
        : "=r"(a) : "l"(p));
    return a;
}
__device__ __forceinline__ void mbar_init(unsigned mbar, unsigned count) {
    asm volatile("mbarrier.init.shared.b64 [%0], %1;" :: "r"(mbar), "r"(count)
                 : "memory");
}
__device__ __forceinline__ void mbar_expect_tx(unsigned mbar, unsigned bytes) {
    asm volatile("mbarrier.arrive.expect_tx.shared.b64 _, [%0], %1;"
                 :: "r"(mbar), "r"(bytes) : "memory");
}
// Remote 8B store; completion (with data-visibility guarantee) signaled to the
// DESTINATION CTA's mbarrier via complete_tx — no fences needed.
__device__ __forceinline__ void dsmem_st_async64(unsigned laddr, unsigned lmbar,
                                                 unsigned rank, unsigned long long v) {
    asm volatile(
        "{ .reg .b32 ra, rm;\n\t"
        "mapa.shared::cluster.u32 ra, %0, %2;\n\t"
        "mapa.shared::cluster.u32 rm, %1, %2;\n\t"
        "st.async.shared::cluster.mbarrier::complete_tx::bytes.b64 [ra], %3, [rm]; }"
        :: "r"(laddr), "r"(lmbar), "r"(rank), "l"(v) : "memory");
}
__device__ __forceinline__ void mbar_wait(unsigned mbar, unsigned parity) {
    unsigned done;
    asm volatile(
        "{ .reg .pred p;\n\t"
        "mbarrier.try_wait.parity.acquire.cta.shared::cta.b64 p, [%1], %2;\n\t"
        "selp.b32 %0, 1, 0, p; }"
        : "=r"(done) : "r"(mbar), "r"(parity) : "memory");
    while (!done) {
        asm volatile(
            "{ .reg .pred p;\n\t"
            "mbarrier.try_wait.parity.acquire.cta.shared::cta.b64 p, [%1], %2, 0x989680;\n\t"
            "selp.b32 %0, 1, 0, p; }"
            : "=r"(done) : "r"(mbar), "r"(parity) : "memory");
    }
}
#define CLUSTER_SYNC_() do {                                        \
    asm volatile("barrier.cluster.arrive.aligned;" ::: "memory");   \
    asm volatile("barrier.cluster.wait.aligned;"   ::: "memory");   \
} while (0)

// ============================================================
// Kernel A: X @ Wg + bg for g in {z, r, h} (fp32, FFMA2).
// Output layout: Xg[((t*8 + n/32)*16 + b/4)*128 + (b%4)*32 + (n%32)]
// ============================================================
__global__ __launch_bounds__(256) void x_proj_kernel(
    const float* __restrict__ X,
    const float* __restrict__ Wz, const float* __restrict__ Wr, const float* __restrict__ Wh,
    const float* __restrict__ bz, const float* __restrict__ br, const float* __restrict__ bh)
{
    const int tid = threadIdx.x;
    const float* W; const float* bias; float* out;
    if (blockIdx.z == 0)      { W = Wz; bias = bz; out = g_Xz; }
    else if (blockIdx.z == 1) { W = Wr; bias = br; out = g_Xr; }
    else                      { W = Wh; bias = bh; out = g_Xh; }

    __shared__ __align__(16) float As[32][68];  // transposed X tile: As[k][row]
    __shared__ __align__(16) float Ws[32][68];  // W tile: Ws[k][col]

    const int tx = tid & 15;          // 4 cols each
    const int ty = tid >> 4;          // 4 rows each (rows = batch)
    const int t = blockIdx.x;
    const int col0 = blockIdx.y * 64;

    unsigned long long acc2[4][2];
#pragma unroll
    for (int i = 0; i < 4; i++) { acc2[i][0] = 0ull; acc2[i][1] = 0ull; }

    for (int kk = 0; kk < DIM; kk += 32) {
#pragma unroll
        for (int li = 0; li < 2; li++) {
            int idx = li * 256 + tid;
            int r = idx >> 3;
            int q = idx & 7;
            float4 v = *(const float4*)&X[(t * 64 + r) * DIM + kk + q * 4];
            As[q * 4 + 0][r] = v.x;
            As[q * 4 + 1][r] = v.y;
            As[q * 4 + 2][r] = v.z;
            As[q * 4 + 3][r] = v.w;
        }
#pragma unroll
        for (int li = 0; li < 2; li++) {
            int idx = li * 256 + tid;
            int k = idx >> 4;
            int q = idx & 15;
            float4 v = *(const float4*)&W[(kk + k) * DIM + col0 + q * 4];
            *(float4*)&Ws[k][q * 4] = v;
        }
        __syncthreads();
#pragma unroll 8
        for (int k = 0; k < 32; k++) {
            float4 a = *(const float4*)&As[k][ty * 4];
            ulonglong2 w2 = *(const ulonglong2*)&Ws[k][tx * 4];
            unsigned long long d0 = pack2(a.x, a.x);
            unsigned long long d1 = pack2(a.y, a.y);
            unsigned long long d2 = pack2(a.z, a.z);
            unsigned long long d3 = pack2(a.w, a.w);
            ffma2(acc2[0][0], d0, w2.x); ffma2(acc2[0][1], d0, w2.y);
            ffma2(acc2[1][0], d1, w2.x); ffma2(acc2[1][1], d1, w2.y);
            ffma2(acc2[2][0], d2, w2.x); ffma2(acc2[2][1], d2, w2.y);
            ffma2(acc2[3][0], d3, w2.x); ffma2(acc2[3][1], d3, w2.y);
        }
        __syncthreads();
    }

    float4 bias4 = __ldg((const float4*)&bias[col0 + tx * 4]);
    const int ngx = blockIdx.y * 2 + (tx >> 3);
    const int nl0 = (tx & 7) * 4;
#pragma unroll
    for (int i = 0; i < 4; i++) {
        float2 p0 = unpack2(acc2[i][0]);
        float2 p1 = unpack2(acc2[i][1]);
        float4 v = make_float4(p0.x + bias4.x, p0.y + bias4.y,
                               p1.x + bias4.z, p1.y + bias4.w);
        *(float4*)&out[((t * NN + ngx) * NB + ty) * 128 + i * 32 + nl0] = v;
    }
}

// ============================================================
// Kernel B: persistent recurrence, 128 CTAs, clusters of 8.
// Warp-autonomous: warp w owns columns w*4..w*4+3; lane l = kq*4+col
// covers k = kq+8i (i<32) for its column, all 4 batches. Reduction over
// the 8 kq lanes via 3 shfl.xor rounds — NO syncthreads in the loop.
// Exchange via st.async + complete_tx into depth-2 buffers (hsA/hsB x2,
// parity (t>>1)&1): buffer reuse at t+2 is transitively gated by the tx
// protocol because every warp contains owner lanes.
// ============================================================
__global__ __launch_bounds__(256, 1) __cluster_dims__(NN, 1, 1)
void gru_rec_kernel(
    const float* __restrict__ Uh, const float* __restrict__ Ur,
    const float* __restrict__ Uz, const float* __restrict__ h0,
    float* __restrict__ out)
{
    __shared__ __align__(16) float4 hsA[2][256];   // h(t):   [t&1][k][bl]
    __shared__ __align__(16) float4 hsB[2][256];   // r*h(t): [t&1][k][bl]
    __shared__ __align__(8)  unsigned long long mbars[4];   // A0 A1 B0 B1

    const int tid  = threadIdx.x;
    const int w    = tid >> 5;
    const int l    = tid & 31;
    const int col  = l & 3;                     // column within warp's group
    const int kq   = l >> 2;                    // k-phase 0..7
    const int bg   = blockIdx.x >> 3;           // cluster id = batch group
    const unsigned ng = blockIdx.x & (NN - 1);  // rank in cluster
    const int n_g  = (int)ng * NPG + w * 4 + col;   // global column 0..255

    const unsigned mA0 = smem_u32(&mbars[0]);
    const unsigned mA1 = smem_u32(&mbars[1]);
    const unsigned mB0 = smem_u32(&mbars[2]);
    const unsigned mB1 = smem_u32(&mbars[3]);
    const unsigned hsA0 = smem_u32(&hsA[0][0]);
    const unsigned hsA1 = smem_u32(&hsA[1][0]);
    const unsigned hsB0 = smem_u32(&hsB[0][0]);
    const unsigned hsB1 = smem_u32(&hsB[1][0]);

    // loop-invariant U slices in registers: u*[i] = U[(kq+8i)*256 + n_g]
    float uz[32], ur[32], uh[32];
#pragma unroll
    for (int i = 0; i < 32; i++) {
        int k = kq + 8 * i;
        uz[i] = __ldg(&Uz[k * DIM + n_g]);
        ur[i] = __ldg(&Ur[k * DIM + n_g]);
        uh[i] = __ldg(&Uh[k * DIM + n_g]);
    }

    if (tid == 0) {
        mbar_init(mA0, 1); mbar_init(mA1, 1);
        mbar_init(mB0, 1); mbar_init(mB1, 1);
        mbar_expect_tx(mA0, TX_BYTES); mbar_expect_tx(mA1, TX_BYTES);
        mbar_expect_tx(mB0, TX_BYTES); mbar_expect_tx(mB1, TX_BYTES);
    }
    __syncthreads();
    CLUSTER_SYNC_();                    // barriers armed before any st.async

    const bool owner = (kq < 2);        // lanes 0..7 of every warp
    const int bp = kq;                  // owner's batch pair (0/1)
    const int b0 = bg * BPG + bp * 2;   // owner's first global batch
    const unsigned push_off = (unsigned)(n_g * 16 + bp * 8);

    float hp0 = 0.f, hp1 = 0.f;
    if (owner) {
        float v = __ldg(&h0[n_g]);      // init hidden, broadcast over batch
        hp0 = v; hp1 = v;
        unsigned long long pv = pack2(hp0, hp1);
#pragma unroll
        for (unsigned p = 0; p < NN; p++)
            dsmem_st_async64(hsA0 + push_off, mA0, p, pv);
    }

    float zp0, zp1, rp0, rp1;
    float xz0, xz1, xr0, xr1, xh0, xh1;

    for (int t = 0; t < T_STEPS; t++) {
        const int bi = t & 1;
        const unsigned pr = (unsigned)((t >> 1) & 1);
        const unsigned mA = bi ? mA1 : mA0;
        const unsigned mB = bi ? mB1 : mB0;
        const float4* hA = hsA[bi];
        const float4* hB = hsB[bi];

        if (owner) {
            // x projections (independent of h; overlap the wait below)
            int a0 = ((t * NN + (int)ng) * NB + bg) * 128 + bp * 64 + (w * 4 + col);
            xz0 = __ldg(&g_Xz[a0]); xz1 = __ldg(&g_Xz[a0 + 32]);
            xr0 = __ldg(&g_Xr[a0]); xr1 = __ldg(&g_Xr[a0 + 32]);
            xh0 = __ldg(&g_Xh[a0]); xh1 = __ldg(&g_Xh[a0 + 32]);
            // emit PRE-update hidden (reference semantics)
            out[(t * BATCH + b0) * DIM + n_g]     = hp0;
            out[(t * BATCH + b0 + 1) * DIM + n_g] = hp1;
        }

        // ---- phase 1: wait for h(t), z & r matvecs ----
        mbar_wait(mA, pr);
        if (tid == 0 && t + 2 < T_STEPS) mbar_expect_tx(mA, TX_BYTES);

        unsigned long long az01 = 0, az23 = 0, ar01 = 0, ar23 = 0;
#pragma unroll
        for (int i = 0; i < 32; i++) {
            ulonglong2 hk = *(const ulonglong2*)&hA[kq + 8 * i];
            unsigned long long a = pack2(uz[i], uz[i]);
            unsigned long long c = pack2(ur[i], ur[i]);
            ffma2(az01, hk.x, a); ffma2(az23, hk.y, a);
            ffma2(ar01, hk.x, c); ffma2(ar23, hk.y, c);
        }
#pragma unroll
        for (int m = 4; m <= 16; m <<= 1) {
            az01 = addf2(az01, shflx64(az01, m));
            az23 = addf2(az23, shflx64(az23, m));
            ar01 = addf2(ar01, shflx64(ar01, m));
            ar23 = addf2(ar23, shflx64(ar23, m));
        }

        if (owner) {
            float2 az = unpack2(bp ? az23 : az01);
            float2 ar = unpack2(bp ? ar23 : ar01);
            zp0 = sigmoidf_(az.x + xz0); zp1 = sigmoidf_(az.y + xz1);
            rp0 = sigmoidf_(ar.x + xr0); rp1 = sigmoidf_(ar.y + xr1);
            unsigned long long pv = pack2(rp0 * hp0, rp1 * hp1);
            unsigned dst = (bi ? hsB1 : hsB0) + push_off;
#pragma unroll
            for (unsigned p = 0; p < NN; p++) dsmem_st_async64(dst, mB, p, pv);
        }

        // ---- phase 2: wait for r*h(t), h_bar matvec, combine, publish ----
        mbar_wait(mB, pr);
        if (tid == 0 && t + 2 < T_STEPS) mbar_expect_tx(mB, TX_BYTES);

        unsigned long long ah01 = 0, ah23 = 0;
#pragma unroll
        for (int i = 0; i < 32; i++) {
            ulonglong2 hk = *(const ulonglong2*)&hB[kq + 8 * i];
            unsigned long long a = pack2(uh[i], uh[i]);
            ffma2(ah01, hk.x, a); ffma2(ah23, hk.y, a);
        }
#pragma unroll
        for (int m = 4; m <= 16; m <<= 1) {
            ah01 = addf2(ah01, shflx64(ah01, m));
            ah23 = addf2(ah23, shflx64(ah23, m));
        }

        if (owner) {
            float2 ah = unpack2(bp ? ah23 : ah01);
            float hb0 = tanh_clamped(ah.x + xh0);
            float hb1 = tanh_clamped(ah.y + xh1);
            hp0 = (1.0f - rp0) * hp0 + zp0 * hb0;   // (1-r) per reference
            hp1 = (1.0f - rp1) * hp1 + zp1 * hb1;
            if (t + 1 < T_STEPS) {                  // no in-flight ops at exit
                unsigned long long pv = pack2(hp0, hp1);
                unsigned dst = (((t + 1) & 1) ? hsA1 : hsA0) + push_off;
                unsigned mAn = (((t + 1) & 1) ? mA1 : mA0);
#pragma unroll
                for (unsigned p = 0; p < NN; p++)
                    dsmem_st_async64(dst, mAn, p, pv);
            }
        }
    }

    CLUSTER_SYNC_();    // no CTA exits while peers might still touch its smem
}

extern "C" void kernel_launch(void* const* d_in, const int* in_sizes, int n_in,
                              void* d_out, int out_size)
{
    const float* X   = (const float*)d_in[0];
    const float* W   = (const float*)d_in[1];
    const float* U   = (const float*)d_in[2];
    const float* bh  = (const float*)d_in[3];
    const float* W_r = (const float*)d_in[4];
    const float* U_r = (const float*)d_in[5];
    const float* b_r = (const float*)d_in[6];
    const float* W_z = (const float*)d_in[7];
    const float* U_z = (const float*)d_in[8];
    const float* b_z = (const float*)d_in[9];
    const float* h0  = (const float*)d_in[10];
    float* out = (float*)d_out;

    x_proj_kernel<<<dim3(T_STEPS, 4, 3), 256>>>(X, W_z, W_r, W, b_z, b_r, bh);
    gru_rec_kernel<<<NCTA, 256>>>(U, U_r, U_z, h0, out);
}